// round 7
// baseline (speedup 1.0000x reference)
#include <cuda_runtime.h>
#include <cstdint>

// Unpool (max_unpool_with_argmax inverse), input-centric, ILP=4:
// each thread owns 4 input float4 chunks (block-strided, coalesced), loads all
// val+mask up front (MLP=8), then emits 16 independent 2x2-window streaming
// stores. out[o] = (mask == o) ? val : 0. Mask is int32 (JAX x64 off).
//
// Shapes: val (16,64,64,128) f32, mask same int32, out (16,128,128,128) f32.

namespace {
constexpr int IN_VEC  = (16 * 64 * 64 * 128) / 4;  // 2,097,152 float4 chunks
constexpr int ILP     = 4;
constexpr int THREADS = 256;
}

__global__ __launch_bounds__(THREADS) void unpool_scatter4_ilp4_kernel(
    const float4* __restrict__ val4,
    const int4*   __restrict__ mask4,
    float4*       __restrict__ out4)
{
    const int t0 = blockIdx.x * (THREADS * ILP) + threadIdx.x;

    // Batch all loads first: 8 outstanding requests per thread.
    float4 v[ILP];
    int4   m[ILP];
    #pragma unroll
    for (int j = 0; j < ILP; ++j) {
        const int t = t0 + j * THREADS;
        v[j] = __ldg(&val4[t]);
        m[j] = __ldg(&mask4[t]);
    }

    #pragma unroll
    for (int j = 0; j < ILP; ++j) {
        const int t = t0 + j * THREADS;
        const int i = t << 2;               // flat input element index

        const int c = i & 127;
        const int w = (i >> 7)  & 63;
        const int h = (i >> 13) & 63;
        const int b = i >> 19;

        // Output flat base: (b<<21) + (2h<<14) + (2w<<7) + c
        const int base = (b << 21) + (h << 15) + (w << 8) + c;

        #pragma unroll
        for (int dh = 0; dh < 2; ++dh) {
            #pragma unroll
            for (int dw = 0; dw < 2; ++dw) {
                const int o = base + (dh << 14) + (dw << 7);
                float4 r;
                r.x = (m[j].x == o    ) ? v[j].x : 0.0f;
                r.y = (m[j].y == o + 1) ? v[j].y : 0.0f;
                r.z = (m[j].z == o + 2) ? v[j].z : 0.0f;
                r.w = (m[j].w == o + 3) ? v[j].w : 0.0f;
                __stcs(&out4[o >> 2], r);   // streaming: keep inputs in L2
            }
        }
    }
}

extern "C" void kernel_launch(void* const* d_in, const int* in_sizes, int n_in,
                              void* d_out, int out_size)
{
    const float4* val4  = (const float4*)d_in[0];
    const int4*   mask4 = (const int4*)d_in[1];
    float4*       out4  = (float4*)d_out;

    const int blocks = IN_VEC / (THREADS * ILP);   // 2048

    unpool_scatter4_ilp4_kernel<<<blocks, THREADS>>>(val4, mask4, out4);
}

// round 8
// speedup vs baseline: 1.0623x; 1.0623x over previous
#include <cuda_runtime.h>
#include <cstdint>

// Unpool (max_unpool_with_argmax inverse), input-centric:
// one thread loads one val float4 + mask int4 and emits the four 2x2-window
// output float4s with write-through stores (bypass L2 allocation so the
// 134MB output stream doesn't churn the L2-resident 67MB of inputs).
// out[o] = (mask == o) ? val : 0. Mask is int32 (JAX x64 off).
//
// Shapes: val (16,64,64,128) f32, mask same int32, out (16,128,128,128) f32.

namespace {
constexpr int C  = 128;
constexpr int IN_ELEMS = 16 * 64 * 64 * 128;   // 8,388,608
}

__device__ __forceinline__ void st_wt_f4(float4* p, float4 r) {
    asm volatile("st.global.wt.v4.f32 [%0], {%1,%2,%3,%4};"
                 :: "l"(p), "f"(r.x), "f"(r.y), "f"(r.z), "f"(r.w)
                 : "memory");
}

__global__ __launch_bounds__(256) void unpool_scatter4_wt_kernel(
    const float4* __restrict__ val4,
    const int4*   __restrict__ mask4,
    float4*       __restrict__ out4)
{
    const int t = blockIdx.x * blockDim.x + threadIdx.x;   // < 2^21
    const int i = t << 2;                                  // flat input elem idx

    const int c = i & (C - 1);
    const int w = (i >> 7)  & 63;
    const int h = (i >> 13) & 63;
    const int b = i >> 19;

    const float4 v = __ldg(&val4[t]);
    const int4   m = __ldg(&mask4[t]);

    // Output flat base: (b<<21) + (2h<<14) + (2w<<7) + c
    const int base = (b << 21) + (h << 15) + (w << 8) + c;

    #pragma unroll
    for (int dh = 0; dh < 2; ++dh) {
        #pragma unroll
        for (int dw = 0; dw < 2; ++dw) {
            const int o = base + (dh << 14) + (dw << 7);
            float4 r;
            r.x = (m.x == o    ) ? v.x : 0.0f;
            r.y = (m.y == o + 1) ? v.y : 0.0f;
            r.z = (m.z == o + 2) ? v.z : 0.0f;
            r.w = (m.w == o + 3) ? v.w : 0.0f;
            st_wt_f4(&out4[o >> 2], r);
        }
    }
}

extern "C" void kernel_launch(void* const* d_in, const int* in_sizes, int n_in,
                              void* d_out, int out_size)
{
    const float4* val4  = (const float4*)d_in[0];
    const int4*   mask4 = (const int4*)d_in[1];
    float4*       out4  = (float4*)d_out;

    const int n_vec   = IN_ELEMS >> 2;       // 2,097,152 threads
    const int threads = 256;
    const int blocks  = n_vec / threads;     // 8192

    unpool_scatter4_wt_kernel<<<blocks, threads>>>(val4, mask4, out4);
}